// round 6
// baseline (speedup 1.0000x reference)
#include <cuda_runtime.h>
#include <cstdint>

#define NROWS  65536
#define DIN    64
#define NC     1024
#define DOUT   256
#define BM     64
#define BK     32
#define NCHUNK (NC / BK)
#define THREADS 256
#define CSTRIDE 68
#define PSTRIDE 36
#define VSTRIDE 264
#define LOG2E  1.4426950408889634f

struct Smem {
    float    cs[BK][CSTRIDE];   // centers chunk (raw c)
    float    csq[BK];           // sum c^2 s
    uint32_t p[BM][PSTRIDE];    // P chunk, tf32 bits
    uint32_t vs[BK][VSTRIDE];   // V chunk, tf32 bits
    float    rowsum[BM];
    float    s[DIN];
};

__device__ __forceinline__ uint32_t f2tf32(float f) {
    uint32_t u;
    asm("cvt.rna.tf32.f32 %0, %1;" : "=r"(u) : "f"(f));
    return u;
}
__device__ __forceinline__ float fast_exp2(float f) {
    float r;
    asm("ex2.approx.f32 %0, %1;" : "=f"(r) : "f"(f));
    return r;
}
__device__ __forceinline__ void mma8(float* d, const uint32_t* a,
                                     uint32_t b0, uint32_t b1) {
    asm volatile(
        "mma.sync.aligned.m16n8k8.row.col.f32.tf32.tf32.f32 "
        "{%0,%1,%2,%3}, {%4,%5,%6,%7}, {%8,%9}, {%0,%1,%2,%3};"
        : "+f"(d[0]), "+f"(d[1]), "+f"(d[2]), "+f"(d[3])
        : "r"(a[0]), "r"(a[1]), "r"(a[2]), "r"(a[3]), "r"(b0), "r"(b1));
}

__global__ void __launch_bounds__(THREADS, 1)
attnn_mma_kernel(const float* __restrict__ x,
                 const float* __restrict__ ctrs,
                 const float* __restrict__ values,
                 const float* __restrict__ s_in,
                 float* __restrict__ out)
{
    extern __shared__ char raw[];
    Smem& sm = *reinterpret_cast<Smem*>(raw);

    const int tid  = threadIdx.x;
    const int lane = tid & 31;
    const int wid  = tid >> 5;
    const int r    = tid >> 2;        // stage-1 row 0..63
    const int q    = tid & 3;         // stage-1 d-slice (16 d's)
    const int n0   = blockIdx.x * BM;

    // loader mapping (centers & V)
    const int ck = tid >> 3;          // 0..31 (k row)
    const int cd = (tid & 7) * 8;     // ctrs d base
    const int vc = (tid & 7) * 4;     // V col base (stride 32)

    // stage-3 mma mapping
    const int rw  = wid >> 1;         // row group: rows rw*16 .. +16
    const int wc  = wid & 1;          // col group: cols wc*128 .. +128
    const int grp = lane >> 2;
    const int thr = lane & 3;
    const int m0  = rw * 16 + grp;

    if (tid < DIN) sm.s[tid] = s_in[tid];
    __syncthreads();

    // ---- persistent x slice in regs: xr = 2*s*x ----
    float xr[16];
    {
        const float* xp = x + (size_t)(n0 + r) * DIN + 16 * q;
        #pragma unroll
        for (int m = 0; m < 4; m++) {
            float4 v = *reinterpret_cast<const float4*>(xp + 4 * m);
            const int d = 16 * q + 4 * m;
            xr[4*m+0] = 2.f * v.x * sm.s[d+0];
            xr[4*m+1] = 2.f * v.y * sm.s[d+1];
            xr[4*m+2] = 2.f * v.z * sm.s[d+2];
            xr[4*m+3] = 2.f * v.w * sm.s[d+3];
        }
    }
    // persistent s slice for csq
    float sreg[8];
    #pragma unroll
    for (int u = 0; u < 8; u++) sreg[u] = sm.s[cd + u];

    // ---- prefetch chunk 0 ----
    float4 cpre0, cpre1, vpre[8];
    {
        const float* cp = ctrs + (size_t)ck * DIN + cd;
        cpre0 = *reinterpret_cast<const float4*>(cp);
        cpre1 = *reinterpret_cast<const float4*>(cp + 4);
        const float* vp = values + (size_t)ck * DOUT + vc;
        #pragma unroll
        for (int j = 0; j < 8; j++)
            vpre[j] = *reinterpret_cast<const float4*>(vp + 32 * j);
    }

    float acc[16][4];
    #pragma unroll
    for (int nt = 0; nt < 16; nt++)
        #pragma unroll
        for (int u = 0; u < 4; u++) acc[nt][u] = 0.f;
    float sacc = 0.f;

    for (int chunk = 0; chunk < NCHUNK; chunk++) {
        __syncthreads();   // prev chunk's mma done reading p/vs

        // ---- commit prefetched centers + csq ----
        *reinterpret_cast<float4*>(&sm.cs[ck][cd])     = cpre0;
        *reinterpret_cast<float4*>(&sm.cs[ck][cd + 4]) = cpre1;
        {
            float part = cpre0.x*cpre0.x*sreg[0] + cpre0.y*cpre0.y*sreg[1]
                       + cpre0.z*cpre0.z*sreg[2] + cpre0.w*cpre0.w*sreg[3]
                       + cpre1.x*cpre1.x*sreg[4] + cpre1.y*cpre1.y*sreg[5]
                       + cpre1.z*cpre1.z*sreg[6] + cpre1.w*cpre1.w*sreg[7];
            part += __shfl_xor_sync(0xffffffffu, part, 4);
            part += __shfl_xor_sync(0xffffffffu, part, 2);
            part += __shfl_xor_sync(0xffffffffu, part, 1);
            if ((tid & 7) == 0) sm.csq[ck] = part;
        }
        // ---- commit prefetched V (cvt to tf32) ----
        #pragma unroll
        for (int j = 0; j < 8; j++) {
            uint4 t;
            t.x = f2tf32(vpre[j].x); t.y = f2tf32(vpre[j].y);
            t.z = f2tf32(vpre[j].z); t.w = f2tf32(vpre[j].w);
            *reinterpret_cast<uint4*>(&sm.vs[ck][vc + 32 * j]) = t;
        }
        __syncthreads();

        // ---- prefetch next chunk (hidden behind stage-1 + stage-3) ----
        if (chunk + 1 < NCHUNK) {
            const int kb = (chunk + 1) * BK;
            const float* cp = ctrs + (size_t)(kb + ck) * DIN + cd;
            cpre0 = *reinterpret_cast<const float4*>(cp);
            cpre1 = *reinterpret_cast<const float4*>(cp + 4);
            const float* vp = values + (size_t)(kb + ck) * DOUT + vc;
            #pragma unroll
            for (int j = 0; j < 8; j++)
                vpre[j] = *reinterpret_cast<const float4*>(vp + 32 * j);
        }

        // ---- stage 1: partial cross terms (this thread's 16 d's, all 32 k) ----
        float cr[32];
        #pragma unroll
        for (int k = 0; k < 32; k++) cr[k] = 0.f;
        #pragma unroll
        for (int k = 0; k < 32; k++) {
            #pragma unroll
            for (int m = 0; m < 4; m++) {
                float4 c4 = *reinterpret_cast<const float4*>(&sm.cs[k][16 * q + 4 * m]);
                cr[k] += xr[4*m+0] * c4.x + xr[4*m+1] * c4.y
                       + xr[4*m+2] * c4.z + xr[4*m+3] * c4.w;
            }
        }

        // ---- branch-free reduce-scatter over the 4 d-slices ----
        float r2[16];
        #pragma unroll
        for (int u = 0; u < 16; u++) {
            float lo = cr[u]      + __shfl_xor_sync(0xffffffffu, cr[u], 2);
            float hi = cr[16 + u] + __shfl_xor_sync(0xffffffffu, cr[16 + u], 2);
            r2[u] = (q < 2) ? lo : hi;
        }
        float vfin[8];
        #pragma unroll
        for (int u = 0; u < 8; u++) {
            float lo = r2[u]     + __shfl_xor_sync(0xffffffffu, r2[u], 1);
            float hi = r2[8 + u] + __shfl_xor_sync(0xffffffffu, r2[8 + u], 1);
            vfin[u] = ((q & 1) == 0) ? lo : hi;
        }
        // lane (r,q) now owns full cross for k = 8q + u

        // ---- exp (x^2 term dropped: softmax-invariant), tf32, store P ----
        {
            const int kb = 8 * q;
            uint4 lo4, hi4;
            uint32_t pt[8];
            #pragma unroll
            for (int u = 0; u < 8; u++) {
                float l  = vfin[u] - sm.csq[kb + u];
                float pv = fast_exp2(l * LOG2E);
                uint32_t t = f2tf32(pv);
                sacc += __uint_as_float(t);   // normalize consistently with tf32 P
                pt[u] = t;
            }
            lo4 = make_uint4(pt[0], pt[1], pt[2], pt[3]);
            hi4 = make_uint4(pt[4], pt[5], pt[6], pt[7]);
            *reinterpret_cast<uint4*>(&sm.p[r][kb])     = lo4;
            *reinterpret_cast<uint4*>(&sm.p[r][kb + 4]) = hi4;
        }
        __syncthreads();

        // ---- stage 3: acc += P(64x32) @ V(32x256) via mma.sync tf32 ----
        uint32_t a[4][4];
        #pragma unroll
        for (int kt = 0; kt < 4; kt++) {
            a[kt][0] = sm.p[m0][kt * 8 + thr];
            a[kt][1] = sm.p[m0 + 8][kt * 8 + thr];
            a[kt][2] = sm.p[m0][kt * 8 + thr + 4];
            a[kt][3] = sm.p[m0 + 8][kt * 8 + thr + 4];
        }
        #pragma unroll
        for (int nt = 0; nt < 16; nt++) {
            const int n = wc * 128 + nt * 8 + grp;
            #pragma unroll
            for (int kt = 0; kt < 4; kt++) {
                uint32_t b0 = sm.vs[kt * 8 + thr][n];
                uint32_t b1 = sm.vs[kt * 8 + thr + 4][n];
                mma8(acc[nt], a[kt], b0, b1);
            }
        }
    }

    // ---- row sums -> smem ----
    sacc += __shfl_xor_sync(0xffffffffu, sacc, 1);
    sacc += __shfl_xor_sync(0xffffffffu, sacc, 2);
    if (q == 0) sm.rowsum[r] = sacc;
    __syncthreads();

    // ---- epilogue: normalize + store ----
    {
        const float inv0 = 1.0f / sm.rowsum[m0];
        const float inv1 = 1.0f / sm.rowsum[m0 + 8];
        float* o0 = out + (size_t)(n0 + m0) * DOUT;
        float* o1 = out + (size_t)(n0 + m0 + 8) * DOUT;
        #pragma unroll
        for (int nt = 0; nt < 16; nt++) {
            const int col = wc * 128 + nt * 8 + 2 * thr;
            float2 s0 = make_float2(acc[nt][0] * inv0, acc[nt][1] * inv0);
            float2 s1 = make_float2(acc[nt][2] * inv1, acc[nt][3] * inv1);
            *reinterpret_cast<float2*>(o0 + col) = s0;
            *reinterpret_cast<float2*>(o1 + col) = s1;
        }
    }
}

extern "C" void kernel_launch(void* const* d_in, const int* in_sizes, int n_in,
                              void* d_out, int out_size)
{
    const float* x      = (const float*)d_in[0];   // (65536, 64)
    const float* ctrs   = (const float*)d_in[1];   // (1024, 64)
    const float* values = (const float*)d_in[2];   // (1024, 256)
    const float* s      = (const float*)d_in[3];   // (64,)
    float* out          = (float*)d_out;           // (65536, 256)

    const int smem_bytes = (int)sizeof(Smem);
    cudaFuncSetAttribute(attnn_mma_kernel,
                         cudaFuncAttributeMaxDynamicSharedMemorySize, smem_bytes);
    attnn_mma_kernel<<<NROWS / BM, THREADS, smem_bytes>>>(x, ctrs, values, s, out);
}

// round 7
// speedup vs baseline: 1.4457x; 1.4457x over previous
#include <cuda_runtime.h>
#include <cstdint>

#define NROWS  65536
#define DIN    64
#define NC     1024
#define DOUT   256
#define BM     64
#define BK     32
#define NCHUNK (NC / BK)
#define THREADS 256
#define CSTRIDE 68
#define PSTRIDE 36
#define VSTRIDE 36
#define LOG2E  1.4426950408889634f

struct Smem {
    float    cs[2][BK][CSTRIDE];    // centers, d-block swizzled
    float    csq[2][BK];            // sum c^2 s
    uint32_t p[2][BM][PSTRIDE];     // P chunk, tf32 bits
    uint32_t vt[2][DOUT][VSTRIDE];  // V^T chunk, tf32 bits (vt[n][k])
    float    rowsum[BM];
    float    s[DIN];
};

__device__ __forceinline__ uint32_t f2tf32(float f) {
    uint32_t u;
    asm("cvt.rna.tf32.f32 %0, %1;" : "=r"(u) : "f"(f));
    return u;
}
__device__ __forceinline__ float fast_exp2(float f) {
    float r;
    asm("ex2.approx.f32 %0, %1;" : "=f"(r) : "f"(f));
    return r;
}
__device__ __forceinline__ void mma8(float* d, const uint32_t* a,
                                     uint32_t b0, uint32_t b1) {
    asm volatile(
        "mma.sync.aligned.m16n8k8.row.col.f32.tf32.tf32.f32 "
        "{%0,%1,%2,%3}, {%4,%5,%6,%7}, {%8,%9}, {%0,%1,%2,%3};"
        : "+f"(d[0]), "+f"(d[1]), "+f"(d[2]), "+f"(d[3])
        : "r"(a[0]), "r"(a[1]), "r"(a[2]), "r"(a[3]), "r"(b0), "r"(b1));
}

// stage 3: acc += P(64x32) @ V(32x256); warp tile M32 x N64, conflict-free LDS
__device__ __forceinline__ void stage3(const Smem& sm, int bb, int rw, int wc,
                                       int grp, int thr, float acc[2][8][4]) {
    uint32_t a[2][4][4];
    #pragma unroll
    for (int mt = 0; mt < 2; mt++) {
        const int m = rw * 32 + mt * 16 + grp;
        #pragma unroll
        for (int kt = 0; kt < 4; kt++) {
            a[mt][kt][0] = sm.p[bb][m][8 * kt + thr];
            a[mt][kt][1] = sm.p[bb][m + 8][8 * kt + thr];
            a[mt][kt][2] = sm.p[bb][m][8 * kt + thr + 4];
            a[mt][kt][3] = sm.p[bb][m + 8][8 * kt + thr + 4];
        }
    }
    #pragma unroll
    for (int nt = 0; nt < 8; nt++) {
        const int n = wc * 64 + nt * 8 + grp;
        #pragma unroll
        for (int kt = 0; kt < 4; kt++) {
            const uint32_t b0 = sm.vt[bb][n][8 * kt + thr];
            const uint32_t b1 = sm.vt[bb][n][8 * kt + thr + 4];
            mma8(acc[0][nt], a[0][kt], b0, b1);   // b-frag reused for both
            mma8(acc[1][nt], a[1][kt], b0, b1);   // row tiles
        }
    }
}

__global__ void __launch_bounds__(THREADS, 1)
attnn_kernel(const float* __restrict__ x,
             const float* __restrict__ ctrs,
             const float* __restrict__ values,
             const float* __restrict__ s_in,
             float* __restrict__ out)
{
    extern __shared__ char raw[];
    Smem& sm = *reinterpret_cast<Smem*>(raw);

    const int tid  = threadIdx.x;
    const int lane = tid & 31;
    const int wid  = tid >> 5;
    const int r    = tid >> 2;        // stage-1 row 0..63
    const int q    = tid & 3;         // stage-1 d-slice
    const int n0   = blockIdx.x * BM;

    const int ck = tid >> 3;          // loader k row 0..31
    const int cd = (tid & 7) * 8;     // ctrs d base
    const int nb = tid & 7;           // V col base (n = nb + 8j)

    const int rw  = wid >> 2;         // stage-3 row warp 0..1
    const int wc  = wid & 3;          // stage-3 col warp 0..3
    const int grp = lane >> 2;
    const int thr = lane & 3;

    if (tid < DIN) sm.s[tid] = s_in[tid];
    __syncthreads();

    // ---- persistent x slice: xr = 2*s*x ----
    float xr[16];
    {
        const float* xp = x + (size_t)(n0 + r) * DIN + 16 * q;
        #pragma unroll
        for (int m = 0; m < 4; m++) {
            float4 v = *reinterpret_cast<const float4*>(xp + 4 * m);
            const int d = 16 * q + 4 * m;
            xr[4*m+0] = 2.f * v.x * sm.s[d+0];
            xr[4*m+1] = 2.f * v.y * sm.s[d+1];
            xr[4*m+2] = 2.f * v.z * sm.s[d+2];
            xr[4*m+3] = 2.f * v.w * sm.s[d+3];
        }
    }
    float sreg[8];
    #pragma unroll
    for (int u = 0; u < 8; u++) sreg[u] = sm.s[cd + u];

    // stage-1 read slots (bank-despread swizzle) and ctrs store slots
    int slot[4];
    #pragma unroll
    for (int m = 0; m < 4; m++) slot[m] = 16 * q + 4 * ((m + q) & 3);
    const int q0s = cd >> 4, m0s = (cd >> 2) & 3;
    const int cslot0 = 16 * q0s + 4 * ((m0s + q0s) & 3);
    const int cslot1 = 16 * q0s + 4 * ((m0s + 1 + q0s) & 3);

    float acc[2][8][4];
    #pragma unroll
    for (int mt = 0; mt < 2; mt++)
        #pragma unroll
        for (int nt = 0; nt < 8; nt++)
            #pragma unroll
            for (int u = 0; u < 4; u++) acc[mt][nt][u] = 0.f;
    float sacc = 0.f;

    for (int c = 0; c < NCHUNK; c++) {
        const int b  = c & 1;
        const int kc = c * BK;
        if (c) __syncthreads();     // all warps done with previous iter body

        // ---- commit centers (swizzled) + csq ----
        {
            const float* cp = ctrs + (size_t)(kc + ck) * DIN + cd;
            float4 c0 = *reinterpret_cast<const float4*>(cp);
            float4 c1 = *reinterpret_cast<const float4*>(cp + 4);
            *reinterpret_cast<float4*>(&sm.cs[b][ck][cslot0]) = c0;
            *reinterpret_cast<float4*>(&sm.cs[b][ck][cslot1]) = c1;
            float part = c0.x*c0.x*sreg[0] + c0.y*c0.y*sreg[1]
                       + c0.z*c0.z*sreg[2] + c0.w*c0.w*sreg[3]
                       + c1.x*c1.x*sreg[4] + c1.y*c1.y*sreg[5]
                       + c1.z*c1.z*sreg[6] + c1.w*c1.w*sreg[7];
            part += __shfl_xor_sync(0xffffffffu, part, 4);
            part += __shfl_xor_sync(0xffffffffu, part, 2);
            part += __shfl_xor_sync(0xffffffffu, part, 1);
            if ((tid & 7) == 0) sm.csq[b][ck] = part;
        }
        // ---- commit V transposed (conflict-free STS) ----
        {
            const float* vp = values + (size_t)(kc + ck) * DOUT + nb;
            float vtmp[32];
            #pragma unroll
            for (int j = 0; j < 32; j++) vtmp[j] = vp[8 * j];
            #pragma unroll
            for (int j = 0; j < 32; j++)
                sm.vt[b][nb + 8 * j][ck] = f2tf32(vtmp[j]);
        }
        __syncthreads();

        // ---- stage 3 for previous chunk (overlaps with stage 1 below) ----
        if (c) stage3(sm, 1 - b, rw, wc, grp, thr, acc);

        // ---- stage 1: cross terms for this chunk ----
        float cr[32];
        #pragma unroll
        for (int k = 0; k < 32; k++) cr[k] = 0.f;
        #pragma unroll
        for (int k = 0; k < 32; k++) {
            #pragma unroll
            for (int m = 0; m < 4; m++) {
                float4 c4 = *reinterpret_cast<const float4*>(&sm.cs[b][k][slot[m]]);
                cr[k] += xr[4*m+0] * c4.x + xr[4*m+1] * c4.y
                       + xr[4*m+2] * c4.z + xr[4*m+3] * c4.w;
            }
        }
        // reduce-scatter over 4 d-slices
        float r2[16];
        #pragma unroll
        for (int u = 0; u < 16; u++) {
            float lo = cr[u]      + __shfl_xor_sync(0xffffffffu, cr[u], 2);
            float hi = cr[16 + u] + __shfl_xor_sync(0xffffffffu, cr[16 + u], 2);
            r2[u] = (q < 2) ? lo : hi;
        }
        float vfin[8];
        #pragma unroll
        for (int u = 0; u < 8; u++) {
            float lo = r2[u]     + __shfl_xor_sync(0xffffffffu, r2[u], 1);
            float hi = r2[8 + u] + __shfl_xor_sync(0xffffffffu, r2[8 + u], 1);
            vfin[u] = ((q & 1) == 0) ? lo : hi;
        }
        // exp (x^2 term dropped: softmax-invariant), tf32, store P
        {
            const int kb = 8 * q;
            uint32_t pt[8];
            #pragma unroll
            for (int u = 0; u < 8; u++) {
                float l  = vfin[u] - sm.csq[b][kb + u];
                float pv = fast_exp2(l * LOG2E);
                pt[u] = f2tf32(pv);
                sacc += __uint_as_float(pt[u]);
            }
            *reinterpret_cast<uint4*>(&sm.p[b][r][kb]) =
                make_uint4(pt[0], pt[1], pt[2], pt[3]);
            *reinterpret_cast<uint4*>(&sm.p[b][r][kb + 4]) =
                make_uint4(pt[4], pt[5], pt[6], pt[7]);
        }
    }

    __syncthreads();   // P[31] / vt[31] visible

    // ---- row sums (overlap with final stage 3) ----
    sacc += __shfl_xor_sync(0xffffffffu, sacc, 1);
    sacc += __shfl_xor_sync(0xffffffffu, sacc, 2);
    if (q == 0) sm.rowsum[r] = sacc;

    stage3(sm, (NCHUNK - 1) & 1, rw, wc, grp, thr, acc);
    __syncthreads();

    // ---- epilogue: normalize + store ----
    #pragma unroll
    for (int mt = 0; mt < 2; mt++) {
        const int row0 = rw * 32 + mt * 16 + grp;
        const float inv0 = 1.0f / sm.rowsum[row0];
        const float inv1 = 1.0f / sm.rowsum[row0 + 8];
        float* o0 = out + (size_t)(n0 + row0) * DOUT;
        float* o1 = out + (size_t)(n0 + row0 + 8) * DOUT;
        #pragma unroll
        for (int nt = 0; nt < 8; nt++) {
            const int col = wc * 64 + nt * 8 + 2 * thr;
            *reinterpret_cast<float2*>(o0 + col) =
                make_float2(acc[mt][nt][0] * inv0, acc[mt][nt][1] * inv0);
            *reinterpret_cast<float2*>(o1 + col) =
                make_float2(acc[mt][nt][2] * inv1, acc[mt][nt][3] * inv1);
        }
    }
}

extern "C" void kernel_launch(void* const* d_in, const int* in_sizes, int n_in,
                              void* d_out, int out_size)
{
    const float* x      = (const float*)d_in[0];   // (65536, 64)
    const float* ctrs   = (const float*)d_in[1];   // (1024, 64)
    const float* values = (const float*)d_in[2];   // (1024, 256)
    const float* s      = (const float*)d_in[3];   // (64,)
    float* out          = (float*)d_out;           // (65536, 256)

    const int smem_bytes = (int)sizeof(Smem);
    cudaFuncSetAttribute(attnn_kernel,
                         cudaFuncAttributeMaxDynamicSharedMemorySize, smem_bytes);
    attnn_kernel<<<NROWS / BM, THREADS, smem_bytes>>>(x, ctrs, values, s, out);
}

// round 11
// speedup vs baseline: 2.4988x; 1.7285x over previous
#include <cuda_runtime.h>
#include <cstdint>

#define NROWS  65536
#define DIN    64
#define NC     1024
#define DOUT   256
#define BM     64
#define BK     32
#define NCHUNK (NC / BK)
#define THREADS 256
#define CSTRIDE 68
#define PSTRIDE 36
#define VSTRIDE 36
#define LOG2E  1.4426950408889634f

struct Smem {
    uint32_t ct_hi[2][BK][CSTRIDE];   // centers hi (tf32 bits), [n][d]
    uint32_t ct_lo[2][BK][CSTRIDE];   // centers lo
    uint32_t vt[2][DOUT][VSTRIDE];    // V^T (tf32 bits), [n][k]
    uint32_t p[2][BM][PSTRIDE];       // P (tf32 bits), [m][k]
    float    csq[2][BK];              // sum c^2 s
    float    rowsum[2][BM];           // per-n-half partial row sums
    float    s[DIN];
};

__device__ __forceinline__ uint32_t f2tf32(float f) {
    uint32_t u;
    asm("cvt.rna.tf32.f32 %0, %1;" : "=r"(u) : "f"(f));
    return u;
}
__device__ __forceinline__ float fast_exp2(float f) {
    float r;
    asm("ex2.approx.f32 %0, %1;" : "=f"(r) : "f"(f));
    return r;
}
__device__ __forceinline__ void mma8(float* d, const uint32_t* a,
                                     uint32_t b0, uint32_t b1) {
    asm volatile(
        "mma.sync.aligned.m16n8k8.row.col.f32.tf32.tf32.f32 "
        "{%0,%1,%2,%3}, {%4,%5,%6,%7}, {%8,%9}, {%0,%1,%2,%3};"
        : "+f"(d[0]), "+f"(d[1]), "+f"(d[2]), "+f"(d[3])
        : "r"(a[0]), "r"(a[1]), "r"(a[2]), "r"(a[3]), "r"(b0), "r"(b1));
}

// GEMM2: acc += P(64x32) @ V(32x256); warp tile M32 x N64, conflict-free LDS
__device__ __forceinline__ void gemm2(const Smem& sm, int bb, int rw, int wc,
                                      int grp, int thr, float acc[2][8][4]) {
    uint32_t a[2][4][4];
    #pragma unroll
    for (int mt = 0; mt < 2; mt++) {
        const int m = rw * 32 + mt * 16 + grp;
        #pragma unroll
        for (int kt = 0; kt < 4; kt++) {
            a[mt][kt][0] = sm.p[bb][m][8 * kt + thr];
            a[mt][kt][1] = sm.p[bb][m + 8][8 * kt + thr];
            a[mt][kt][2] = sm.p[bb][m][8 * kt + thr + 4];
            a[mt][kt][3] = sm.p[bb][m + 8][8 * kt + thr + 4];
        }
    }
    #pragma unroll
    for (int nt = 0; nt < 8; nt++) {
        const int n = wc * 64 + nt * 8 + grp;
        #pragma unroll
        for (int kt = 0; kt < 4; kt++) {
            const uint32_t b0 = sm.vt[bb][n][8 * kt + thr];
            const uint32_t b1 = sm.vt[bb][n][8 * kt + thr + 4];
            mma8(acc[0][nt], a[0][kt], b0, b1);
            mma8(acc[1][nt], a[1][kt], b0, b1);
        }
    }
}

__global__ void __launch_bounds__(THREADS, 1)
attnn_kernel(const float* __restrict__ x,
             const float* __restrict__ ctrs,
             const float* __restrict__ values,
             const float* __restrict__ s_in,
             float* __restrict__ out)
{
    extern __shared__ char raw[];
    Smem& sm = *reinterpret_cast<Smem*>(raw);

    const int tid  = threadIdx.x;
    const int lane = tid & 31;
    const int wid  = tid >> 5;
    const int n0   = blockIdx.x * BM;

    // loader mapping
    const int ck = tid >> 3;          // k row 0..31
    const int cd = (tid & 7) * 8;     // ctrs d base
    const int nb = tid & 7;           // V col base

    // mma lane mapping
    const int grp = lane >> 2;
    const int thr = lane & 3;
    // GEMM1 warp mapping: m-tile (16 rows) x n-half (16 cols)
    const int g1m  = (wid & 3) * 16;
    const int half = wid >> 2;
    // GEMM2 warp mapping: m-half (32 rows) x n-quarter (64 cols)
    const int rw = wid >> 2;
    const int wc = wid & 3;

    if (tid < DIN) sm.s[tid] = s_in[tid];
    __syncthreads();

    // ---- stage x (2*s*x) into smem scratch (overlays vt, prologue only) ----
    float* xs = reinterpret_cast<float*>(&sm.vt[0][0][0]);   // [64][68]
    {
        const int r = tid >> 2, q = tid & 3;
        const float* xp = x + (size_t)(n0 + r) * DIN + 16 * q;
        #pragma unroll
        for (int m = 0; m < 4; m++) {
            float4 v = *reinterpret_cast<const float4*>(xp + 4 * m);
            const int d = 16 * q + 4 * m;
            float4 t = make_float4(2.f * v.x * sm.s[d+0], 2.f * v.y * sm.s[d+1],
                                   2.f * v.z * sm.s[d+2], 2.f * v.w * sm.s[d+3]);
            *reinterpret_cast<float4*>(&xs[r * 68 + d]) = t;
        }
    }
    // persistent s slice for csq
    float sreg[8];
    #pragma unroll
    for (int u = 0; u < 8; u++) sreg[u] = sm.s[cd + u];

    // ---- prefetch chunk 0 (LDG overlaps with frag extraction) ----
    float4 cpre0, cpre1;
    float  vpre[32];
    {
        const float* cp = ctrs + (size_t)ck * DIN + cd;
        cpre0 = *reinterpret_cast<const float4*>(cp);
        cpre1 = *reinterpret_cast<const float4*>(cp + 4);
        const float* vp = values + (size_t)ck * DOUT + nb;
        #pragma unroll
        for (int j = 0; j < 32; j++) vpre[j] = vp[8 * j];
    }
    __syncthreads();

    // ---- extract persistent x hi/lo A-fragments (m16k8 x 8 ksteps) ----
    uint32_t xh[8][4], xl[8][4];
    #pragma unroll
    for (int kt = 0; kt < 8; kt++) {
        float v[4];
        v[0] = xs[(g1m + grp)     * 68 + 8 * kt + thr];
        v[1] = xs[(g1m + grp + 8) * 68 + 8 * kt + thr];
        v[2] = xs[(g1m + grp)     * 68 + 8 * kt + thr + 4];
        v[3] = xs[(g1m + grp + 8) * 68 + 8 * kt + thr + 4];
        #pragma unroll
        for (int u = 0; u < 4; u++) {
            xh[kt][u] = f2tf32(v[u]);
            xl[kt][u] = f2tf32(v[u] - __uint_as_float(xh[kt][u]));
        }
    }
    __syncthreads();   // xs scratch free -> vt usable

    float acc[2][8][4];
    #pragma unroll
    for (int mt = 0; mt < 2; mt++)
        #pragma unroll
        for (int nt = 0; nt < 8; nt++)
            #pragma unroll
            for (int u = 0; u < 4; u++) acc[mt][nt][u] = 0.f;
    float sacc0 = 0.f, sacc1 = 0.f;

    for (int c = 0; c < NCHUNK; c++) {
        const int b = c & 1;

        // ---- commit centers hi/lo + csq ----
        {
            uint4 h0, h1, l0, l1;
            h0.x = f2tf32(cpre0.x); l0.x = f2tf32(cpre0.x - __uint_as_float(h0.x));
            h0.y = f2tf32(cpre0.y); l0.y = f2tf32(cpre0.y - __uint_as_float(h0.y));
            h0.z = f2tf32(cpre0.z); l0.z = f2tf32(cpre0.z - __uint_as_float(h0.z));
            h0.w = f2tf32(cpre0.w); l0.w = f2tf32(cpre0.w - __uint_as_float(h0.w));
            h1.x = f2tf32(cpre1.x); l1.x = f2tf32(cpre1.x - __uint_as_float(h1.x));
            h1.y = f2tf32(cpre1.y); l1.y = f2tf32(cpre1.y - __uint_as_float(h1.y));
            h1.z = f2tf32(cpre1.z); l1.z = f2tf32(cpre1.z - __uint_as_float(h1.z));
            h1.w = f2tf32(cpre1.w); l1.w = f2tf32(cpre1.w - __uint_as_float(h1.w));
            *reinterpret_cast<uint4*>(&sm.ct_hi[b][ck][cd])     = h0;
            *reinterpret_cast<uint4*>(&sm.ct_hi[b][ck][cd + 4]) = h1;
            *reinterpret_cast<uint4*>(&sm.ct_lo[b][ck][cd])     = l0;
            *reinterpret_cast<uint4*>(&sm.ct_lo[b][ck][cd + 4]) = l1;
            float part = cpre0.x*cpre0.x*sreg[0] + cpre0.y*cpre0.y*sreg[1]
                       + cpre0.z*cpre0.z*sreg[2] + cpre0.w*cpre0.w*sreg[3]
                       + cpre1.x*cpre1.x*sreg[4] + cpre1.y*cpre1.y*sreg[5]
                       + cpre1.z*cpre1.z*sreg[6] + cpre1.w*cpre1.w*sreg[7];
            part += __shfl_xor_sync(0xffffffffu, part, 4);
            part += __shfl_xor_sync(0xffffffffu, part, 2);
            part += __shfl_xor_sync(0xffffffffu, part, 1);
            if ((tid & 7) == 0) sm.csq[b][ck] = part;
        }
        // ---- commit V transposed (conflict-free STS.32) ----
        #pragma unroll
        for (int j = 0; j < 32; j++)
            sm.vt[b][nb + 8 * j][ck] = f2tf32(vpre[j]);
        __syncthreads();   // sync1: tiles visible

        // ---- prefetch next chunk ----
        if (c + 1 < NCHUNK) {
            const int kb = (c + 1) * BK;
            const float* cp = ctrs + (size_t)(kb + ck) * DIN + cd;
            cpre0 = *reinterpret_cast<const float4*>(cp);
            cpre1 = *reinterpret_cast<const float4*>(cp + 4);
            const float* vp = values + (size_t)(kb + ck) * DOUT + nb;
            #pragma unroll
            for (int j = 0; j < 32; j++) vpre[j] = vp[8 * j];
        }

        // ---- GEMM1: logits via 3xTF32 (M64 x N32 x K64) ----
        float pacc[2][4];
        #pragma unroll
        for (int nt = 0; nt < 2; nt++)
            #pragma unroll
            for (int u = 0; u < 4; u++) pacc[nt][u] = 0.f;
        #pragma unroll
        for (int nt = 0; nt < 2; nt++) {
            const int n = half * 16 + nt * 8 + grp;
            #pragma unroll
            for (int kt = 0; kt < 8; kt++) {
                const uint32_t bh0 = sm.ct_hi[b][n][8 * kt + thr];
                const uint32_t bh1 = sm.ct_hi[b][n][8 * kt + thr + 4];
                const uint32_t bl0 = sm.ct_lo[b][n][8 * kt + thr];
                const uint32_t bl1 = sm.ct_lo[b][n][8 * kt + thr + 4];
                mma8(pacc[nt], xh[kt], bh0, bh1);
                mma8(pacc[nt], xh[kt], bl0, bl1);
                mma8(pacc[nt], xl[kt], bh0, bh1);
            }
        }

        // ---- exp in fragment (x^2 term dropped: softmax-invariant), store P ----
        #pragma unroll
        for (int nt = 0; nt < 2; nt++) {
            const int c0 = half * 16 + nt * 8 + 2 * thr;
            const float2 cq = *reinterpret_cast<const float2*>(&sm.csq[b][c0]);
            uint32_t p0 = f2tf32(fast_exp2((pacc[nt][0] - cq.x) * LOG2E));
            uint32_t p1 = f2tf32(fast_exp2((pacc[nt][1] - cq.y) * LOG2E));
            uint32_t p2 = f2tf32(fast_exp2((pacc[nt][2] - cq.x) * LOG2E));
            uint32_t p3 = f2tf32(fast_exp2((pacc[nt][3] - cq.y) * LOG2E));
            sacc0 += __uint_as_float(p0) + __uint_as_float(p1);
            sacc1 += __uint_as_float(p2) + __uint_as_float(p3);
            *reinterpret_cast<uint2*>(&sm.p[b][g1m + grp][c0])     = make_uint2(p0, p1);
            *reinterpret_cast<uint2*>(&sm.p[b][g1m + grp + 8][c0]) = make_uint2(p2, p3);
        }
        __syncthreads();   // sync2: P visible

        // ---- GEMM2 ----
        gemm2(sm, b, rw, wc, grp, thr, acc);
    }

    // ---- combine row sums: reduce over thr quad, then over 2 n-halves ----
    sacc0 += __shfl_xor_sync(0xffffffffu, sacc0, 1);
    sacc0 += __shfl_xor_sync(0xffffffffu, sacc0, 2);
    sacc1 += __shfl_xor_sync(0xffffffffu, sacc1, 1);
    sacc1 += __shfl_xor_sync(0xffffffffu, sacc1, 2);
    if (thr == 0) {
        sm.rowsum[half][g1m + grp]     = sacc0;
        sm.rowsum[half][g1m + grp + 8] = sacc1;
    }
    __syncthreads();

    // ---- epilogue: normalize + store ----
    #pragma unroll
    for (int mt = 0; mt < 2; mt++) {
        const int row0 = rw * 32 + mt * 16 + grp;
        const float inv0 = 1.0f / (sm.rowsum[0][row0]     + sm.rowsum[1][row0]);
        const float inv1 = 1.0f / (sm.rowsum[0][row0 + 8] + sm.rowsum[1][row0 + 8]);
        float* o0 = out + (size_t)(n0 + row0) * DOUT;
        float* o1 = out + (size_t)(n0 + row0 + 8) * DOUT;
        #pragma unroll
        for (int nt = 0; nt < 8; nt++) {
            const int col = wc * 64 + nt * 8 + 2 * thr;
            *reinterpret_cast<float2*>(o0 + col) =
                make_float2(acc[mt][nt][0] * inv0, acc[mt][nt][1] * inv0);
            *reinterpret_cast<float2*>(o1 + col) =
                make_float2(acc[mt][nt][2] * inv1, acc[mt][nt][3] * inv1);
        }
    }
}

extern "C" void kernel_launch(void* const* d_in, const int* in_sizes, int n_in,
                              void* d_out, int out_size)
{
    const float* x      = (const float*)d_in[0];   // (65536, 64)
    const float* ctrs   = (const float*)d_in[1];   // (1024, 64)
    const float* values = (const float*)d_in[2];   // (1024, 256)
    const float* s      = (const float*)d_in[3];   // (64,)
    float* out          = (float*)d_out;           // (65536, 256)

    const int smem_bytes = (int)sizeof(Smem);
    cudaFuncSetAttribute(attnn_kernel,
                         cudaFuncAttributeMaxDynamicSharedMemorySize, smem_bytes);
    attnn_kernel<<<NROWS / BM, THREADS, smem_bytes>>>(x, ctrs, values, s, out);
}